// round 15
// baseline (speedup 1.0000x reference)
#include <cuda_runtime.h>
#include <stdint.h>

// QLayerOriginal: rho <- U rho U^dagger over 16 blocks of 3 angles.
// Exact reduction: on the complex Bloch vector t (rho = t0 I + t.sigma),
// conjugation by U(p0,p1,p2)=D(p1/2)R(p0/2)D(p2/2) is the REAL SO(3) map
// Rz(-p1) Ry(p0) Rz(-p2) on Re(t), Im(t); t0 invariant. Adjacent Rz fuse
// (zacc carries previous p1):
//   zacc=0; for k: Rz(-(zacc+phi[3k+2])); Ry(phi[3k]); zacc=phi[3k+1]; final Rz(-zacc).
//
// R15: FOUR cp.async quarter-groups (12 floats = 4 rotation blocks each).
// wait(3) -> compute Q0 while Q1..Q3 in flight; wait(2) -> Q1; wait(1) -> Q2;
// wait(0) -> Q3. Memory in flight during ~3/4 of compute (R14: 1/2), raising
// DRAM duty cycle. Quarter-row stride 12 floats: cp.async dst 16B-aligned,
// float4 phi-pass conflict-free per phase, scalar reads 4-way (same as R14).
// Each thread computes with only its own row; barriers are for cp.async
// cross-thread visibility only.

#define NTHREADS 96
#define ROWS NTHREADS
#define QF 12                   // floats per quarter-row

__device__ __forceinline__ void cp_async16(uint32_t dst, const void* src) {
    asm volatile("cp.async.cg.shared.global [%0], [%1], 16;" :: "r"(dst), "l"(src));
}
#define CP_COMMIT()  asm volatile("cp.async.commit_group;" ::: "memory")
#define CP_WAIT(n)   asm volatile("cp.async.wait_group %0;" :: "n"(n) : "memory")

__global__ void __launch_bounds__(NTHREADS) qlayer_kernel_vec(
    const float* __restrict__ rho_real,
    const float* __restrict__ rho_imag,
    const float* __restrict__ x,
    const float* __restrict__ w,
    const float* __restrict__ theta,
    float* __restrict__ out,
    long long nbatch,
    long long out_elems,
    int full_complex)
{
    __shared__ float buf[4][ROWS * QF];   // 4*96*12*4 = 18432 B
    __shared__ float s_w[48];
    __shared__ float s_t[48];

    int tid = threadIdx.x;
    long long blockBase = (long long)blockIdx.x * ROWS;
    long long nLocal = nbatch - blockBase;
    if (nLocal > ROWS) nLocal = ROWS;

    if (tid < 12) {
        ((float4*)s_w)[tid] = __ldg((const float4*)w + tid);
        ((float4*)s_t)[tid] = __ldg((const float4*)theta + tid);
    }

    int j3 = tid % 3;            // float4 within a quarter-row
    int sq = tid / 3;            // 0..31
    const float4* xg = (const float4*)x + blockBase * 12;

    // ---- issue 4 quarter groups ----
#pragma unroll
    for (int q = 0; q < 4; ++q) {
        uint32_t qbase = (uint32_t)__cvta_generic_to_shared(&buf[q][0]);
#pragma unroll
        for (int k = 0; k < 3; ++k) {
            int s = sq + 32 * k;
            if (s < (int)nLocal)
                cp_async16(qbase + (uint32_t)(s * QF + j3 * 4) * 4u,
                           xg + s * 12 + q * 3 + j3);
        }
        CP_COMMIT();
    }

    long long i = blockBase + tid;
    bool active = (i < nbatch);
    long long iclamp = active ? i : 0;
    float4 rr = __ldcs((const float4*)rho_real + iclamp);
    float4 ri = __ldcs((const float4*)rho_imag + iclamp);

    // ---- Pauli decomposition ----
    float t0r = 0.5f * (rr.x + rr.w), t0i = 0.5f * (ri.x + ri.w);
    float vzr = 0.5f * (rr.x - rr.w), vzi = 0.5f * (ri.x - ri.w);
    float vxr = 0.5f * (rr.y + rr.z), vxi = 0.5f * (ri.y + ri.z);
    float vyr = 0.5f * (ri.z - ri.y), vyi = 0.5f * (rr.y - rr.z);

    float zacc = 0.0f;

    // ---- per-quarter: wait, barrier, phi-pass (own row), 4 rotation blocks ----
#pragma unroll
    for (int q = 0; q < 4; ++q) {
        switch (q) {                 // wait for quarter q; q+1..3 stay in flight
            case 0: CP_WAIT(3); break;
            case 1: CP_WAIT(2); break;
            case 2: CP_WAIT(1); break;
            case 3: CP_WAIT(0); break;
        }
        __syncthreads();

        float* row = &buf[q][tid * QF];
        {   // phi-pass: in-place, float4, conflict-free per phase
            float4* rowv = (float4*)row;
#pragma unroll
            for (int j4 = 0; j4 < 3; ++j4) {
                float4 xv = rowv[j4];
                float4 wv = ((const float4*)s_w)[q * 3 + j4];
                float4 tv = ((const float4*)s_t)[q * 3 + j4];
                rowv[j4] = make_float4(fmaf(xv.x, wv.x, tv.x), fmaf(xv.y, wv.y, tv.y),
                                       fmaf(xv.z, wv.z, tv.z), fmaf(xv.w, wv.w, tv.w));
            }
        }

#pragma unroll
        for (int m = 0; m < 4; ++m) {
            float psi = zacc + row[3 * m + 2];
            float sz, cz;
            __sincosf(psi, &sz, &cz);
            {   // Rz(-psi): x' = c x + s y ; y' = c y - s x
                float nxr = cz * vxr + sz * vyr;
                float nyr = cz * vyr - sz * vxr;
                float nxi = cz * vxi + sz * vyi;
                float nyi = cz * vyi - sz * vxi;
                vxr = nxr; vyr = nyr; vxi = nxi; vyi = nyi;
            }
            float sy, cy;
            __sincosf(row[3 * m], &sy, &cy);
            {   // Ry(a): x' = c x + s z ; z' = c z - s x
                float nxr = cy * vxr + sy * vzr;
                float nzr = cy * vzr - sy * vxr;
                float nxi = cy * vxi + sy * vzi;
                float nzi = cy * vzi - sy * vxi;
                vxr = nxr; vzr = nzr; vxi = nxi; vzi = nzi;
            }
            zacc = row[3 * m + 1];
        }
    }
    {   // final Rz(-zacc)
        float sz, cz;
        __sincosf(zacc, &sz, &cz);
        float nxr = cz * vxr + sz * vyr;
        float nyr = cz * vyr - sz * vxr;
        float nxi = cz * vxi + sz * vyi;
        float nyi = cz * vyi - sz * vxi;
        vxr = nxr; vyr = nyr; vxi = nxi; vyi = nyi;
    }

    if (!active) return;

    // ---- reconstruct & store: r00=t0+tz, r01=tx-i ty, r10=tx+i ty, r11=t0-tz ----
    if (full_complex) {
        long long base = i * 8;
        if (base + 7 < out_elems) {
            float4* op = (float4*)(out + base);
            __stcs(op + 0, make_float4(t0r + vzr, t0i + vzi, vxr + vyi, vxi - vyr));
            __stcs(op + 1, make_float4(vxr - vyi, vxi + vyr, t0r - vzr, t0i - vzi));
        }
    } else {
        long long base = i * 4;
        if (base + 3 < out_elems) {
            __stcs((float4*)(out + base),
                   make_float4(t0r + vzr, vxr + vyi, vxr - vyi, t0r - vzr));
        }
    }
}

// ---- scalar fallback (any alignment) ---------------------------------------
__global__ void __launch_bounds__(128) qlayer_kernel_scalar(
    const float* __restrict__ rho_real,
    const float* __restrict__ rho_imag,
    const float* __restrict__ x,
    const float* __restrict__ w,
    const float* __restrict__ theta,
    float* __restrict__ out,
    long long nbatch,
    long long out_elems,
    int full_complex)
{
    __shared__ float s_w[48];
    __shared__ float s_t[48];
    int tid = threadIdx.x;
    if (tid < 48) {
        s_w[tid] = w[tid];
        s_t[tid] = theta[tid];
    }
    __syncthreads();

    long long i = (long long)blockIdx.x * 128 + tid;
    if (i >= nbatch) return;

    const float* xr = x + i * 48;
#define PHI(j) fmaf(xr[(j)], s_w[(j)], s_t[(j)])

    const float* rrp = rho_real + i * 4;
    const float* rip = rho_imag + i * 4;
    float rr0 = rrp[0], rr1 = rrp[1], rr2 = rrp[2], rr3 = rrp[3];
    float ri0 = rip[0], ri1 = rip[1], ri2 = rip[2], ri3 = rip[3];

    float t0r = 0.5f * (rr0 + rr3), t0i = 0.5f * (ri0 + ri3);
    float vzr = 0.5f * (rr0 - rr3), vzi = 0.5f * (ri0 - ri3);
    float vxr = 0.5f * (rr1 + rr2), vxi = 0.5f * (ri1 + ri2);
    float vyr = 0.5f * (ri2 - ri1), vyi = 0.5f * (rr1 - rr2);

    float zacc = 0.0f;
#pragma unroll
    for (int k = 0; k < 16; ++k) {
        float psi = zacc + PHI(3 * k + 2);
        float sz, cz;
        __sincosf(psi, &sz, &cz);
        {
            float nxr = cz * vxr + sz * vyr;
            float nyr = cz * vyr - sz * vxr;
            float nxi = cz * vxi + sz * vyi;
            float nyi = cz * vyi - sz * vxi;
            vxr = nxr; vyr = nyr; vxi = nxi; vyi = nyi;
        }
        float sy, cy;
        __sincosf(PHI(3 * k), &sy, &cy);
        {
            float nxr = cy * vxr + sy * vzr;
            float nzr = cy * vzr - sy * vxr;
            float nxi = cy * vxi + sy * vzi;
            float nzi = cy * vzi - sy * vxi;
            vxr = nxr; vzr = nzr; vxi = nxi; vzi = nzi;
        }
        zacc = PHI(3 * k + 1);
    }
    {
        float sz, cz;
        __sincosf(zacc, &sz, &cz);
        float nxr = cz * vxr + sz * vyr;
        float nyr = cz * vyr - sz * vxr;
        float nxi = cz * vxi + sz * vyi;
        float nyi = cz * vyi - sz * vxi;
        vxr = nxr; vyr = nyr; vxi = nxi; vyi = nyi;
    }
#undef PHI

    if (full_complex) {
        long long base = i * 8;
        if (base + 7 < out_elems) {
            out[base + 0] = t0r + vzr; out[base + 1] = t0i + vzi;
            out[base + 2] = vxr + vyi; out[base + 3] = vxi - vyr;
            out[base + 4] = vxr - vyi; out[base + 5] = vxi + vyr;
            out[base + 6] = t0r - vzr; out[base + 7] = t0i - vzi;
        }
    } else {
        long long base = i * 4;
        if (base + 3 < out_elems) {
            out[base + 0] = t0r + vzr;
            out[base + 1] = vxr + vyi;
            out[base + 2] = vxr - vyi;
            out[base + 3] = t0r - vzr;
        }
    }
}

extern "C" void kernel_launch(void* const* d_in, const int* in_sizes, int n_in,
                              void* d_out, int out_size)
{
    const float* rho_real = nullptr;
    const float* rho_imag = nullptr;
    const float* x = nullptr;
    const float* w = nullptr;
    const float* theta = nullptr;
    long long B = 0;

    // 1) Strict metadata order (rho_real, rho_imag, x, w, theta).
    if (n_in >= 5) {
        long long s0 = in_sizes[0], s1 = in_sizes[1], s2 = in_sizes[2];
        long long s3 = in_sizes[3], s4 = in_sizes[4];
        if (s0 == s1 && s0 > 0 && (s0 % 4) == 0 &&
            s2 == 12 * s0 && s3 == 48 && s4 == 48) {
            rho_real = (const float*)d_in[0];
            rho_imag = (const float*)d_in[1];
            x        = (const float*)d_in[2];
            w        = (const float*)d_in[3];
            theta    = (const float*)d_in[4];
            B = s0 / 4;
        }
    }

    // 2) Fallback: consistency search over sizes.
    if (B == 0) {
        for (int a = 0; a < n_in && B == 0; ++a) {
            for (int b = a + 1; b < n_in && B == 0; ++b) {
                long long sa = in_sizes[a], sb = in_sizes[b];
                if (sa != sb || sa <= 0 || (sa % 4) != 0) continue;
                long long Bc = sa / 4;
                if (Bc < 2) continue;
                int xk = -1;
                for (int c = 0; c < n_in; ++c) {
                    if (c == a || c == b) continue;
                    if ((long long)in_sizes[c] == 48LL * Bc) { xk = c; break; }
                }
                if (xk < 0) continue;
                int s1i = -1, s2i = -1;
                for (int c = 0; c < n_in; ++c) {
                    if (c == a || c == b || c == xk) continue;
                    if (in_sizes[c] == 48) {
                        if (s1i < 0) s1i = c;
                        else if (s2i < 0) { s2i = c; break; }
                    }
                }
                if (s1i < 0 || s2i < 0) continue;
                rho_real = (const float*)d_in[a];
                rho_imag = (const float*)d_in[b];
                x        = (const float*)d_in[xk];
                w        = (const float*)d_in[s1i];
                theta    = (const float*)d_in[s2i];
                B = Bc;
            }
        }
    }

    float* out = (float*)d_out;
    long long out_elems = (long long)out_size;
    int full_complex = (B > 0 && out_elems >= 8 * B) ? 1 : 0;

    bool aligned =
        (((uintptr_t)x        & 15) == 0) &&
        (((uintptr_t)rho_real & 15) == 0) &&
        (((uintptr_t)rho_imag & 15) == 0) &&
        (((uintptr_t)w        & 15) == 0) &&
        (((uintptr_t)theta    & 15) == 0) &&
        (((uintptr_t)out      & 15) == 0);

    if (B > 0 && aligned) {
        unsigned nblk = (unsigned)((B + ROWS - 1) / ROWS);
        qlayer_kernel_vec<<<nblk, NTHREADS>>>(rho_real, rho_imag, x, w, theta, out,
                                              B, out_elems, full_complex);
    } else {
        unsigned nblk = (unsigned)(B > 0 ? (B + 127) / 128 : 1);
        qlayer_kernel_scalar<<<nblk, 128>>>(rho_real, rho_imag, x, w, theta, out,
                                            B, out_elems, full_complex);
    }
}